// round 6
// baseline (speedup 1.0000x reference)
#include <cuda_runtime.h>
#include <math.h>

// Problem dims (fixed by the dataset)
#define BQ 4
#define LQ 4096
#define DQ 1024
#define HQ 2048
#define BLQ (BQ * LQ)   // 16384 rows

// ---------------------------------------------------------------------------
// Scratch (allocation-free rule: __device__ globals). Reused across phases:
//   g_xn : xn  -> xn2
//   g_b1 : flin -> forget -> u(fc)
//   g_b2 : ilin -> z      -> v(fc_act)
//   g_h  : h   -> ff
//   g_x1 : x1
// ---------------------------------------------------------------------------
__device__ float g_xn[(size_t)BLQ * DQ];
__device__ float g_b1[(size_t)BLQ * HQ];
__device__ float g_b2[(size_t)BLQ * HQ];
__device__ float g_h [(size_t)BLQ * HQ];
__device__ float g_x1[(size_t)BLQ * DQ];

// ---------------------------------------------------------------------------
// RMSNorm: one block per row, D=1024, 256 threads * float4
// ---------------------------------------------------------------------------
__global__ void rmsnorm_kernel(const float* __restrict__ x,
                               const float* __restrict__ g,
                               float* __restrict__ out)
{
    int row = blockIdx.x;
    int tid = threadIdx.x;
    const float4* xr = reinterpret_cast<const float4*>(x + (size_t)row * DQ);
    float4 v = xr[tid];
    float s = v.x * v.x + v.y * v.y + v.z * v.z + v.w * v.w;

    #pragma unroll
    for (int o = 16; o > 0; o >>= 1)
        s += __shfl_xor_sync(0xFFFFFFFFu, s, o);

    __shared__ float red[8];
    __shared__ float scale_s;
    int lane = tid & 31, wid = tid >> 5;
    if (lane == 0) red[wid] = s;
    __syncthreads();
    if (tid == 0) {
        float t = 0.f;
        #pragma unroll
        for (int i = 0; i < 8; i++) t += red[i];
        scale_s = rsqrtf(t * (1.0f / DQ) + 1e-6f);
    }
    __syncthreads();
    float sc = scale_s;
    float4 gg = reinterpret_cast<const float4*>(g)[tid];
    float4 o4;
    o4.x = v.x * sc * gg.x;
    o4.y = v.y * sc * gg.y;
    o4.z = v.z * sc * gg.z;
    o4.w = v.w * sc * gg.w;
    reinterpret_cast<float4*>(out + (size_t)row * DQ)[tid] = o4;
}

// ---------------------------------------------------------------------------
// GEMM: C[M,N] = A[M,K] @ W[N,K]^T + bias[N] (+ resid[M,N] if non-null)
// Tile 128x128, BK=16, 256 threads, 8x8 per-thread microtile. M,N%128==0, K%16==0.
// ---------------------------------------------------------------------------
__global__ __launch_bounds__(256, 2)
void gemm_bias_res(const float* __restrict__ A, const float* __restrict__ W,
                   const float* __restrict__ bias, const float* __restrict__ resid,
                   float* __restrict__ C, int M, int N, int K)
{
    __shared__ float As[16][128];
    __shared__ float Bs[16][128];

    int tid = threadIdx.x;
    int tx = tid & 15;        // 0..15 -> N dir (8 cols each)
    int ty = tid >> 4;        // 0..15 -> M dir (8 rows each)
    int m0 = blockIdx.y * 128;
    int n0 = blockIdx.x * 128;

    float acc[8][8];
    #pragma unroll
    for (int i = 0; i < 8; i++)
        #pragma unroll
        for (int j = 0; j < 8; j++) acc[i][j] = 0.f;

    for (int k0 = 0; k0 < K; k0 += 16) {
        // Load 128x16 tiles of A and W (512 float4 each; 2 per thread)
        #pragma unroll
        for (int it = 0; it < 2; it++) {
            int idx = tid * 2 + it;     // 0..511
            int row = idx >> 2;         // 0..127
            int q   = idx & 3;          // float4 within the 16-wide k-slab
            float4 va = *reinterpret_cast<const float4*>(
                &A[(size_t)(m0 + row) * K + k0 + q * 4]);
            As[q * 4 + 0][row] = va.x;
            As[q * 4 + 1][row] = va.y;
            As[q * 4 + 2][row] = va.z;
            As[q * 4 + 3][row] = va.w;
            float4 vw = *reinterpret_cast<const float4*>(
                &W[(size_t)(n0 + row) * K + k0 + q * 4]);
            Bs[q * 4 + 0][row] = vw.x;
            Bs[q * 4 + 1][row] = vw.y;
            Bs[q * 4 + 2][row] = vw.z;
            Bs[q * 4 + 3][row] = vw.w;
        }
        __syncthreads();

        #pragma unroll
        for (int kk = 0; kk < 16; kk++) {
            float a[8], b[8];
            *reinterpret_cast<float4*>(&a[0]) = *reinterpret_cast<float4*>(&As[kk][ty * 8]);
            *reinterpret_cast<float4*>(&a[4]) = *reinterpret_cast<float4*>(&As[kk][ty * 8 + 4]);
            *reinterpret_cast<float4*>(&b[0]) = *reinterpret_cast<float4*>(&Bs[kk][tx * 8]);
            *reinterpret_cast<float4*>(&b[4]) = *reinterpret_cast<float4*>(&Bs[kk][tx * 8 + 4]);
            #pragma unroll
            for (int i = 0; i < 8; i++)
                #pragma unroll
                for (int j = 0; j < 8; j++)
                    acc[i][j] = fmaf(a[i], b[j], acc[i][j]);
        }
        __syncthreads();
    }

    // Epilogue
    float4 bb0 = *reinterpret_cast<const float4*>(&bias[n0 + tx * 8]);
    float4 bb1 = *reinterpret_cast<const float4*>(&bias[n0 + tx * 8 + 4]);
    #pragma unroll
    for (int i = 0; i < 8; i++) {
        int m = m0 + ty * 8 + i;
        size_t off = (size_t)m * N + n0 + tx * 8;
        float4 r0, r1;
        r0.x = acc[i][0] + bb0.x; r0.y = acc[i][1] + bb0.y;
        r0.z = acc[i][2] + bb0.z; r0.w = acc[i][3] + bb0.w;
        r1.x = acc[i][4] + bb1.x; r1.y = acc[i][5] + bb1.y;
        r1.z = acc[i][6] + bb1.z; r1.w = acc[i][7] + bb1.w;
        if (resid) {
            float4 q0 = *reinterpret_cast<const float4*>(&resid[off]);
            float4 q1 = *reinterpret_cast<const float4*>(&resid[off + 4]);
            r0.x += q0.x; r0.y += q0.y; r0.z += q0.z; r0.w += q0.w;
            r1.x += q1.x; r1.y += q1.y; r1.z += q1.z; r1.w += q1.w;
        }
        *reinterpret_cast<float4*>(&C[off])     = r0;
        *reinterpret_cast<float4*>(&C[off + 4]) = r1;
    }
}

// ---------------------------------------------------------------------------
// Gate elementwise: b1 := forget = 1 - sigmoid(flin)*decay[h]
//                   b2 := z      = tanh(ilin) * sigmoid(flin)*decay[h]
// ---------------------------------------------------------------------------
__global__ void gate_kernel(float* __restrict__ b1, float* __restrict__ b2)
{
    size_t idx = (size_t)blockIdx.x * blockDim.x + threadIdx.x;
    int hh = (int)(idx & (HQ - 1));
    float fl = b1[idx];
    float il = b2[idx];
    float decay = (float)hh * (1.0f / (float)(HQ - 1));
    float rem = (1.0f / (1.0f + expf(-fl))) * decay;
    b1[idx] = 1.0f - rem;
    b2[idx] = tanhf(il) * rem;
}

// ---------------------------------------------------------------------------
// Scan: one thread per (b,h) channel, serial over L. [B,L,H] layout ->
// coalesced loads across the warp at every timestep.
// ---------------------------------------------------------------------------
__global__ void scan_kernel(const float* __restrict__ f, const float* __restrict__ z,
                            const float* __restrict__ h0, float* __restrict__ h,
                            float* __restrict__ hlast)
{
    int c = blockIdx.x * blockDim.x + threadIdx.x;   // 0 .. B*H-1
    int b = c >> 11;                                  // / HQ
    int hh = c & (HQ - 1);
    float hc = h0[c];
    size_t base = (size_t)b * LQ * HQ + hh;
    #pragma unroll 4
    for (int t = 0; t < LQ; t++) {
        size_t idx = base + (size_t)t * HQ;
        hc = fmaf(f[idx], hc, z[idx]);
        h[idx] = hc;
    }
    hlast[c] = hc;
}

// ---------------------------------------------------------------------------
// SwiGLU elementwise: ff = u * silu(v)
// ---------------------------------------------------------------------------
__global__ void swiglu_kernel(const float* __restrict__ u, const float* __restrict__ v,
                              float* __restrict__ ff)
{
    size_t idx = (size_t)blockIdx.x * blockDim.x + threadIdx.x;
    float uu = u[idx];
    float vv = v[idx];
    float sig = 1.0f / (1.0f + expf(-vv));
    ff[idx] = uu * vv * sig;
}

// ---------------------------------------------------------------------------
// Launch
// ---------------------------------------------------------------------------
extern "C" void kernel_launch(void* const* d_in, const int* in_sizes, int n_in,
                              void* d_out, int out_size)
{
    const float* x      = (const float*)d_in[0];
    const float* hidden = (const float*)d_in[1];
    const float* w_f    = (const float*)d_in[2];
    const float* b_f    = (const float*)d_in[3];
    const float* w_i    = (const float*)d_in[4];
    const float* b_i    = (const float*)d_in[5];
    const float* w_ho   = (const float*)d_in[6];
    const float* b_ho   = (const float*)d_in[7];
    const float* w_fc   = (const float*)d_in[8];
    const float* b_fc   = (const float*)d_in[9];
    const float* w_fa   = (const float*)d_in[10];
    const float* b_fa   = (const float*)d_in[11];
    const float* w_fo   = (const float*)d_in[12];
    const float* b_fo   = (const float*)d_in[13];
    const float* g1     = (const float*)d_in[14];
    const float* g2     = (const float*)d_in[15];

    float* out_main  = (float*)d_out;                         // [B,L,D]
    float* out_hlast = out_main + (size_t)BLQ * DQ;           // [B,H]

    float *p_xn, *p_b1, *p_b2, *p_h, *p_x1;
    cudaGetSymbolAddress((void**)&p_xn, g_xn);
    cudaGetSymbolAddress((void**)&p_b1, g_b1);
    cudaGetSymbolAddress((void**)&p_b2, g_b2);
    cudaGetSymbolAddress((void**)&p_h,  g_h);
    cudaGetSymbolAddress((void**)&p_x1, g_x1);

    dim3 blk(256);
    dim3 gemmDH(HQ / 128, BLQ / 128);   // N=2048 outputs
    dim3 gemmHD(DQ / 128, BLQ / 128);   // N=1024 outputs
    size_t nBH = (size_t)BLQ * HQ;

    // 1) xn = rmsnorm(x, g1)
    rmsnorm_kernel<<<BLQ, 256>>>(x, g1, p_xn);
    // 2,3) flin / ilin
    gemm_bias_res<<<gemmDH, blk>>>(p_xn, w_f, b_f, nullptr, p_b1, BLQ, HQ, DQ);
    gemm_bias_res<<<gemmDH, blk>>>(p_xn, w_i, b_i, nullptr, p_b2, BLQ, HQ, DQ);
    // 4) gates
    gate_kernel<<<(unsigned)(nBH / 256), blk>>>(p_b1, p_b2);
    // 5) recurrence -> h, h_last
    scan_kernel<<<(BQ * HQ) / 256, blk>>>(p_b1, p_b2, hidden, p_h, out_hlast);
    // 6) x1 = h @ w_hout^T + b_hout + x
    gemm_bias_res<<<gemmHD, blk>>>(p_h, w_ho, b_ho, x, p_x1, BLQ, DQ, HQ);
    // 7) xn2 = rmsnorm(x1, g2)
    rmsnorm_kernel<<<BLQ, 256>>>(p_x1, g2, p_xn);
    // 8,9) u / v
    gemm_bias_res<<<gemmDH, blk>>>(p_xn, w_fc, b_fc, nullptr, p_b1, BLQ, HQ, DQ);
    gemm_bias_res<<<gemmDH, blk>>>(p_xn, w_fa, b_fa, nullptr, p_b2, BLQ, HQ, DQ);
    // 10) ff = u * silu(v)  (into g_h, h no longer needed)
    swiglu_kernel<<<(unsigned)(nBH / 256), blk>>>(p_b1, p_b2, p_h);
    // 11) out = ff @ w_fout^T + b_fout + x1
    gemm_bias_res<<<gemmHD, blk>>>(p_h, w_fo, b_fo, p_x1, out_main, BLQ, DQ, HQ);
}

// round 8
// speedup vs baseline: 3.1613x; 3.1613x over previous
#include <cuda_runtime.h>
#include <math.h>
#include <stdint.h>

#define BQ 4
#define LQ 4096
#define DQ 1024
#define HQ 2048
#define BLQ 16384

// GEMM tiling
#define BM 128
#define BN 128
#define BK 32
#define NST 3
#define ASTRIDE 36                       // floats per row (32 + 4 pad)
#define TILE_FLOATS (128 * ASTRIDE)      // 4608
#define STAGE_FLOATS (2 * TILE_FLOATS)   // 9216
#define GEMM_SMEM (NST * STAGE_FLOATS * 4)  // 110592 B

// Scratch
__device__ float g_xn[(size_t)BLQ * DQ];
__device__ float g_b1[(size_t)BLQ * HQ];
__device__ float g_b2[(size_t)BLQ * HQ];
__device__ float g_h [(size_t)BLQ * HQ];
__device__ float g_x1[(size_t)BLQ * DQ];
__device__ float g_sA[16 * 8192];
__device__ float g_sB[16 * 8192];
__device__ float g_sS[16 * 8192];

__device__ __forceinline__ void cp_async16(uint32_t saddr, const void* gptr) {
    asm volatile("cp.async.cg.shared.global [%0], [%1], 16;" :: "r"(saddr), "l"(gptr));
}
__device__ __forceinline__ void cp_commit() {
    asm volatile("cp.async.commit_group;" ::: "memory");
}
template <int N>
__device__ __forceinline__ void cp_wait() {
    asm volatile("cp.async.wait_group %0;" :: "n"(N) : "memory");
}
__device__ __forceinline__ uint32_t smem_u32(const void* p) {
    uint32_t a;
    asm("{ .reg .u64 t; cvta.to.shared.u64 t, %1; cvt.u32.u64 %0, t; }"
        : "=r"(a) : "l"(p));
    return a;
}
__device__ __forceinline__ uint32_t f2tf32(float x) {
    uint32_t u;
    asm("cvt.rna.tf32.f32 %0, %1;" : "=r"(u) : "f"(x));
    return u;
}
__device__ __forceinline__ void mma_tf32(float* c, const uint32_t* a, const uint32_t* b) {
    asm volatile(
        "mma.sync.aligned.m16n8k8.row.col.f32.tf32.tf32.f32 "
        "{%0,%1,%2,%3}, {%4,%5,%6,%7}, {%8,%9}, {%0,%1,%2,%3};"
        : "+f"(c[0]), "+f"(c[1]), "+f"(c[2]), "+f"(c[3])
        : "r"(a[0]), "r"(a[1]), "r"(a[2]), "r"(a[3]), "r"(b[0]), "r"(b[1]));
}

// ---------------------------------------------------------------------------
// tf32 mma.sync GEMM: C[M,N] = A[M,K] @ W[N,K]^T + bias (+resid)
// Grid (N/128, M/128), 256 threads, warp tile 64x32.
// ---------------------------------------------------------------------------
__global__ __launch_bounds__(256, 2)
void gemm_tc(const float* __restrict__ A, int K,
             const float* __restrict__ W,
             const float* __restrict__ bias,
             const float* __restrict__ resid,
             float* __restrict__ C, int N)
{
    extern __shared__ float sm[];
    int tid = threadIdx.x;
    int wid = tid >> 5, lane = tid & 31;
    int wm = wid >> 2, wn = wid & 3;        // 2 x 4 warp grid
    int g = lane >> 2, t = lane & 3;        // mma quad indices
    int m0 = blockIdx.y * BM, n0 = blockIdx.x * BN;
    int nk = K >> 5;
    uint32_t sbase = smem_u32(sm);

    float acc[4][4][4];
    #pragma unroll
    for (int i = 0; i < 4; i++)
        #pragma unroll
        for (int j = 0; j < 4; j++)
            #pragma unroll
            for (int r = 0; r < 4; r++) acc[i][j][r] = 0.f;

    // stage loader: 2048 x 16B chunks (A first 1024, B next 1024)
    auto load_stage = [&](int s, int kchunk) {
        uint32_t sa = sbase + s * (STAGE_FLOATS * 4);
        int kb = kchunk * BK;
        #pragma unroll
        for (int i = 0; i < 4; i++) {
            int idx = i * 256 + tid;            // 0..1023
            int row = idx >> 3, c = idx & 7;
            cp_async16(sa + (row * ASTRIDE + c * 4) * 4,
                       A + (size_t)(m0 + row) * K + kb + c * 4);
        }
        #pragma unroll
        for (int i = 0; i < 4; i++) {
            int idx = i * 256 + tid;
            int row = idx >> 3, c = idx & 7;
            cp_async16(sa + (TILE_FLOATS + row * ASTRIDE + c * 4) * 4,
                       W + (size_t)(n0 + row) * K + kb + c * 4);
        }
        cp_commit();
    };

    #pragma unroll
    for (int s = 0; s < NST - 1; s++) load_stage(s, s);

    for (int k0 = 0; k0 < nk; k0++) {
        cp_wait<NST - 2>();
        __syncthreads();
        if (k0 + NST - 1 < nk) load_stage((k0 + NST - 1) % NST, k0 + NST - 1);

        const float* As = sm + (k0 % NST) * STAGE_FLOATS;
        const float* Bs = As + TILE_FLOATS;

        #pragma unroll
        for (int kk = 0; kk < 4; kk++) {
            int kc = kk * 8;
            uint32_t af[4][4], bf[4][2];
            #pragma unroll
            for (int mt = 0; mt < 4; mt++) {
                int r = wm * 64 + mt * 16 + g;
                af[mt][0] = f2tf32(As[r * ASTRIDE + kc + t]);
                af[mt][1] = f2tf32(As[(r + 8) * ASTRIDE + kc + t]);
                af[mt][2] = f2tf32(As[r * ASTRIDE + kc + t + 4]);
                af[mt][3] = f2tf32(As[(r + 8) * ASTRIDE + kc + t + 4]);
            }
            #pragma unroll
            for (int nt = 0; nt < 4; nt++) {
                int n = wn * 32 + nt * 8 + g;
                bf[nt][0] = f2tf32(Bs[n * ASTRIDE + kc + t]);
                bf[nt][1] = f2tf32(Bs[n * ASTRIDE + kc + t + 4]);
            }
            #pragma unroll
            for (int mt = 0; mt < 4; mt++)
                #pragma unroll
                for (int nt = 0; nt < 4; nt++)
                    mma_tf32(acc[mt][nt], af[mt], bf[nt]);
        }
        __syncthreads();
    }

    // epilogue: c0 (r,2t) c1 (r,2t+1) c2 (r+8,2t) c3 (r+8,2t+1)
    #pragma unroll
    for (int mt = 0; mt < 4; mt++) {
        #pragma unroll
        for (int nt = 0; nt < 4; nt++) {
            int row = m0 + wm * 64 + mt * 16 + g;
            int col = n0 + wn * 32 + nt * 8 + 2 * t;
            float2 b2 = *reinterpret_cast<const float2*>(&bias[col]);
            #pragma unroll
            for (int hrow = 0; hrow < 2; hrow++) {
                size_t off = (size_t)(row + hrow * 8) * N + col;
                float2 v;
                v.x = acc[mt][nt][hrow * 2 + 0] + b2.x;
                v.y = acc[mt][nt][hrow * 2 + 1] + b2.y;
                if (resid) {
                    float2 q = *reinterpret_cast<const float2*>(&resid[off]);
                    v.x += q.x; v.y += q.y;
                }
                *reinterpret_cast<float2*>(&C[off]) = v;
            }
        }
    }
}

// ---------------- elementwise ----------------
__global__ void rmsnorm_kernel(const float* __restrict__ x,
                               const float* __restrict__ g,
                               float* __restrict__ out)
{
    int row = blockIdx.x, tid = threadIdx.x;
    float4 v = reinterpret_cast<const float4*>(x + (size_t)row * DQ)[tid];
    float s = v.x * v.x + v.y * v.y + v.z * v.z + v.w * v.w;
    #pragma unroll
    for (int o = 16; o > 0; o >>= 1) s += __shfl_xor_sync(0xFFFFFFFFu, s, o);
    __shared__ float red[8];
    __shared__ float scale_s;
    if ((tid & 31) == 0) red[tid >> 5] = s;
    __syncthreads();
    if (tid == 0) {
        float tt = 0.f;
        #pragma unroll
        for (int i = 0; i < 8; i++) tt += red[i];
        scale_s = rsqrtf(tt * (1.0f / DQ) + 1e-6f);
    }
    __syncthreads();
    float sc = scale_s;
    float4 gg = reinterpret_cast<const float4*>(g)[tid];
    float4 o4 = { v.x * sc * gg.x, v.y * sc * gg.y, v.z * sc * gg.z, v.w * sc * gg.w };
    reinterpret_cast<float4*>(out + (size_t)row * DQ)[tid] = o4;
}

__global__ void gate_kernel(float* __restrict__ b1, float* __restrict__ b2)
{
    size_t i4 = ((size_t)blockIdx.x * blockDim.x + threadIdx.x) * 4;
    int h0 = (int)(i4 & (HQ - 1));
    float4 fl = *reinterpret_cast<float4*>(b1 + i4);
    float4 il = *reinterpret_cast<float4*>(b2 + i4);
    float f[4] = { fl.x, fl.y, fl.z, fl.w };
    float z[4] = { il.x, il.y, il.z, il.w };
    #pragma unroll
    for (int i = 0; i < 4; i++) {
        float decay = (float)(h0 + i) * (1.0f / (float)(HQ - 1));
        float rem = decay / (1.0f + expf(-f[i]));
        f[i] = 1.0f - rem;
        z[i] = tanhf(z[i]) * rem;
    }
    *reinterpret_cast<float4*>(b1 + i4) = make_float4(f[0], f[1], f[2], f[3]);
    *reinterpret_cast<float4*>(b2 + i4) = make_float4(z[0], z[1], z[2], z[3]);
}

// chunked scan: 16 chunks x 256 steps
__global__ void scan_p1(const float* __restrict__ f, const float* __restrict__ z,
                        float* __restrict__ sA, float* __restrict__ sB)
{
    int tg = blockIdx.x * blockDim.x + threadIdx.x;
    int chunk = tg >> 13, c = tg & 8191;
    int b = c >> 11, hh = c & (HQ - 1);
    size_t base = ((size_t)b * LQ + chunk * 256) * HQ + hh;
    float Aa = 1.f, Bb = 0.f;
    #pragma unroll 4
    for (int t = 0; t < 256; t++) {
        size_t i = base + (size_t)t * HQ;
        float ff = f[i];
        Bb = fmaf(ff, Bb, z[i]);
        Aa *= ff;
    }
    sA[tg] = Aa; sB[tg] = Bb;
}

__global__ void scan_p2(const float* __restrict__ h0,
                        const float* __restrict__ sA, const float* __restrict__ sB,
                        float* __restrict__ sS, float* __restrict__ hlast)
{
    int c = blockIdx.x * blockDim.x + threadIdx.x;
    float h = h0[c];
    #pragma unroll
    for (int k = 0; k < 16; k++) {
        sS[k * 8192 + c] = h;
        h = fmaf(sA[k * 8192 + c], h, sB[k * 8192 + c]);
    }
    hlast[c] = h;
}

__global__ void scan_p3(const float* __restrict__ f, const float* __restrict__ z,
                        const float* __restrict__ sS, float* __restrict__ out)
{
    int tg = blockIdx.x * blockDim.x + threadIdx.x;
    int chunk = tg >> 13, c = tg & 8191;
    int b = c >> 11, hh = c & (HQ - 1);
    size_t base = ((size_t)b * LQ + chunk * 256) * HQ + hh;
    float h = sS[tg];
    #pragma unroll 4
    for (int t = 0; t < 256; t++) {
        size_t i = base + (size_t)t * HQ;
        h = fmaf(f[i], h, z[i]);
        out[i] = h;
    }
}

__global__ void swiglu_kernel(const float* __restrict__ u, const float* __restrict__ v,
                              float* __restrict__ ff)
{
    size_t i4 = ((size_t)blockIdx.x * blockDim.x + threadIdx.x) * 4;
    float4 uu = *reinterpret_cast<const float4*>(u + i4);
    float4 vv = *reinterpret_cast<const float4*>(v + i4);
    float4 o;
    o.x = uu.x * vv.x / (1.0f + expf(-vv.x));
    o.y = uu.y * vv.y / (1.0f + expf(-vv.y));
    o.z = uu.z * vv.z / (1.0f + expf(-vv.z));
    o.w = uu.w * vv.w / (1.0f + expf(-vv.w));
    *reinterpret_cast<float4*>(ff + i4) = o;
}

// ---------------- launch ----------------
extern "C" void kernel_launch(void* const* d_in, const int* in_sizes, int n_in,
                              void* d_out, int out_size)
{
    const float* x      = (const float*)d_in[0];
    const float* hidden = (const float*)d_in[1];
    const float* w_f    = (const float*)d_in[2];
    const float* b_f    = (const float*)d_in[3];
    const float* w_i    = (const float*)d_in[4];
    const float* b_i    = (const float*)d_in[5];
    const float* w_ho   = (const float*)d_in[6];
    const float* b_ho   = (const float*)d_in[7];
    const float* w_fc   = (const float*)d_in[8];
    const float* b_fc   = (const float*)d_in[9];
    const float* w_fa   = (const float*)d_in[10];
    const float* b_fa   = (const float*)d_in[11];
    const float* w_fo   = (const float*)d_in[12];
    const float* b_fo   = (const float*)d_in[13];
    const float* g1     = (const float*)d_in[14];
    const float* g2     = (const float*)d_in[15];

    float* out_main  = (float*)d_out;
    float* out_hlast = out_main + (size_t)BLQ * DQ;

    float *xn, *b1, *b2, *h, *x1, *sA, *sB, *sS;
    cudaGetSymbolAddress((void**)&xn, g_xn);
    cudaGetSymbolAddress((void**)&b1, g_b1);
    cudaGetSymbolAddress((void**)&b2, g_b2);
    cudaGetSymbolAddress((void**)&h,  g_h);
    cudaGetSymbolAddress((void**)&x1, g_x1);
    cudaGetSymbolAddress((void**)&sA, g_sA);
    cudaGetSymbolAddress((void**)&sB, g_sB);
    cudaGetSymbolAddress((void**)&sS, g_sS);

    cudaFuncSetAttribute(gemm_tc, cudaFuncAttributeMaxDynamicSharedMemorySize, GEMM_SMEM);

    dim3 gDH(HQ / BN, BLQ / BM);   // (16, 128)
    dim3 gHD(DQ / BN, BLQ / BM);   // (8, 128)

    rmsnorm_kernel<<<BLQ, 256>>>(x, g1, xn);
    gemm_tc<<<gDH, 256, GEMM_SMEM>>>(xn, DQ, w_f, b_f, nullptr, b1, HQ);
    gemm_tc<<<gDH, 256, GEMM_SMEM>>>(xn, DQ, w_i, b_i, nullptr, b2, HQ);
    gate_kernel<<<(BLQ * HQ) / 4 / 256, 256>>>(b1, b2);
    scan_p1<<<512, 256>>>(b1, b2, sA, sB);
    scan_p2<<<32, 256>>>(hidden, sA, sB, sS, out_hlast);
    scan_p3<<<512, 256>>>(b1, b2, sS, h);
    gemm_tc<<<gHD, 256, GEMM_SMEM>>>(h, HQ, w_ho, b_ho, x, x1, DQ);
    rmsnorm_kernel<<<BLQ, 256>>>(x1, g2, xn);
    gemm_tc<<<gDH, 256, GEMM_SMEM>>>(xn, DQ, w_fc, b_fc, nullptr, b1, HQ);
    gemm_tc<<<gDH, 256, GEMM_SMEM>>>(xn, DQ, w_fa, b_fa, nullptr, b2, HQ);
    swiglu_kernel<<<(BLQ * HQ) / 4 / 256, 256>>>(b1, b2, h);
    gemm_tc<<<gHD, 256, GEMM_SMEM>>>(h, HQ, w_fo, b_fo, x1, out_main, DQ);
}

// round 10
// speedup vs baseline: 6.3033x; 1.9939x over previous
#include <cuda_runtime.h>
#include <cuda_fp16.h>
#include <math.h>
#include <stdint.h>

#define BQ 4
#define LQ 4096
#define DQ 1024
#define HQ 2048
#define BLQ 16384

// GEMM tiling (fp16 operands)
#define BM 256
#define BN 128
#define BKH 64                    // halves per k-chunk (128B rows)
#define NST 3
#define A_STAGE 32768             // 256 rows * 128B
#define B_STAGE 16384             // 128 rows * 128B
#define STAGE_B (A_STAGE + B_STAGE)
#define GEMM_SMEM (NST * STAGE_B) // 147456

// Scratch
__device__ __half g_xnh[(size_t)BLQ * DQ];
__device__ __half g_hh [(size_t)BLQ * HQ];
__device__ __half g_wh [6 * (size_t)HQ * DQ];
__device__ float g_b1[(size_t)BLQ * HQ];
__device__ float g_b2[(size_t)BLQ * HQ];
__device__ float g_x1[(size_t)BLQ * DQ];
__device__ float g_sA[16 * 8192];
__device__ float g_sB[16 * 8192];
__device__ float g_sS[16 * 8192];

__device__ __forceinline__ void cp_async16(uint32_t saddr, const void* gptr) {
    asm volatile("cp.async.cg.shared.global [%0], [%1], 16;" :: "r"(saddr), "l"(gptr));
}
__device__ __forceinline__ void cp_commit() {
    asm volatile("cp.async.commit_group;" ::: "memory");
}
template <int N>
__device__ __forceinline__ void cp_wait() {
    asm volatile("cp.async.wait_group %0;" :: "n"(N) : "memory");
}
__device__ __forceinline__ uint32_t smem_u32(const void* p) {
    uint32_t a;
    asm("{ .reg .u64 t; cvta.to.shared.u64 t, %1; cvt.u32.u64 %0, t; }"
        : "=r"(a) : "l"(p));
    return a;
}
__device__ __forceinline__ void ldsm_x4(uint32_t* r, uint32_t addr) {
    asm volatile("ldmatrix.sync.aligned.m8n8.x4.shared.b16 {%0,%1,%2,%3}, [%4];"
        : "=r"(r[0]), "=r"(r[1]), "=r"(r[2]), "=r"(r[3]) : "r"(addr));
}
__device__ __forceinline__ void mma_f16(float* c, const uint32_t* a, const uint32_t* b) {
    asm volatile(
        "mma.sync.aligned.m16n8k16.row.col.f32.f16.f16.f32 "
        "{%0,%1,%2,%3}, {%4,%5,%6,%7}, {%8,%9}, {%0,%1,%2,%3};"
        : "+f"(c[0]), "+f"(c[1]), "+f"(c[2]), "+f"(c[3])
        : "r"(a[0]), "r"(a[1]), "r"(a[2]), "r"(a[3]), "r"(b[0]), "r"(b[1]));
}
#define SWZ(o) ((o) ^ (((o) >> 3) & 0x70))

// ---------------------------------------------------------------------------
// fp16 mma GEMM: C[M,N] = A[M,K]h @ W[N,K]h^T + bias (+resid), fp32 out.
// Grid (N/128, M/256), 256 threads, warp tile 64x64 (4m x 2n warp grid).
// ---------------------------------------------------------------------------
__global__ __launch_bounds__(256, 1)
void gemm_h(const __half* __restrict__ A, int K,
            const __half* __restrict__ W,
            const float* __restrict__ bias,
            const float* __restrict__ resid,
            float* __restrict__ C, int N)
{
    extern __shared__ char sm[];
    int tid = threadIdx.x;
    int wid = tid >> 5, lane = tid & 31;
    int wm = wid >> 1, wn = wid & 1;
    int m0 = blockIdx.y * BM, n0 = blockIdx.x * BN;
    int nk = K / BKH;
    uint32_t sbase = smem_u32(sm);

    float acc[4][8][4];
    #pragma unroll
    for (int i = 0; i < 4; i++)
        #pragma unroll
        for (int j = 0; j < 8; j++)
            #pragma unroll
            for (int r = 0; r < 4; r++) acc[i][j][r] = 0.f;

    auto load_stage = [&](int s, int kc) {
        uint32_t sa = sbase + s * STAGE_B;
        int kb = kc * BKH;
        #pragma unroll
        for (int i = 0; i < 8; i++) {          // A: 2048 chunks of 16B
            int idx = i * 256 + tid;
            int row = idx >> 3, c8 = idx & 7;
            cp_async16(sa + SWZ(row * 128 + c8 * 16),
                       A + (size_t)(m0 + row) * K + kb + c8 * 8);
        }
        #pragma unroll
        for (int i = 0; i < 4; i++) {          // B: 1024 chunks
            int idx = i * 256 + tid;
            int row = idx >> 3, c8 = idx & 7;
            cp_async16(sa + A_STAGE + SWZ(row * 128 + c8 * 16),
                       W + (size_t)(n0 + row) * K + kb + c8 * 8);
        }
        cp_commit();
    };

    #pragma unroll
    for (int s = 0; s < NST - 1; s++) load_stage(s, s);

    for (int k0 = 0; k0 < nk; k0++) {
        cp_wait<NST - 2>();
        __syncthreads();
        if (k0 + NST - 1 < nk) load_stage((k0 + NST - 1) % NST, k0 + NST - 1);

        uint32_t saA = sbase + (k0 % NST) * STAGE_B;
        uint32_t saB = saA + A_STAGE;

        #pragma unroll
        for (int kk = 0; kk < 4; kk++) {
            int kc = kk * 16;
            uint32_t af[4][4], bf[8][2];
            #pragma unroll
            for (int mt = 0; mt < 4; mt++) {
                int row = wm * 64 + mt * 16 + (lane & 15);
                int colh = kc + ((lane >> 4) << 3);
                ldsm_x4(af[mt], saA + SWZ(row * 128 + colh * 2));
            }
            #pragma unroll
            for (int np = 0; np < 4; np++) {
                uint32_t r[4];
                int n = wn * 64 + np * 16 + (lane & 7) + ((lane >> 4) << 3);
                int colh = kc + (((lane >> 3) & 1) << 3);
                ldsm_x4(r, saB + SWZ(n * 128 + colh * 2));
                bf[np * 2 + 0][0] = r[0]; bf[np * 2 + 0][1] = r[1];
                bf[np * 2 + 1][0] = r[2]; bf[np * 2 + 1][1] = r[3];
            }
            #pragma unroll
            for (int mt = 0; mt < 4; mt++)
                #pragma unroll
                for (int nt = 0; nt < 8; nt++)
                    mma_f16(acc[mt][nt], af[mt], bf[nt]);
        }
        __syncthreads();
    }

    int g = lane >> 2, t = lane & 3;
    #pragma unroll
    for (int mt = 0; mt < 4; mt++) {
        #pragma unroll
        for (int nt = 0; nt < 8; nt++) {
            int row = m0 + wm * 64 + mt * 16 + g;
            int col = n0 + wn * 64 + nt * 8 + 2 * t;
            float2 b2 = *reinterpret_cast<const float2*>(&bias[col]);
            #pragma unroll
            for (int hr = 0; hr < 2; hr++) {
                size_t off = (size_t)(row + hr * 8) * N + col;
                float2 v;
                v.x = acc[mt][nt][hr * 2 + 0] + b2.x;
                v.y = acc[mt][nt][hr * 2 + 1] + b2.y;
                if (resid) {
                    float2 q = *reinterpret_cast<const float2*>(&resid[off]);
                    v.x += q.x; v.y += q.y;
                }
                *reinterpret_cast<float2*>(&C[off]) = v;
            }
        }
    }
}

// ---------------- conversions / elementwise ----------------
__global__ void wconv(const float* __restrict__ w, __half* __restrict__ out)
{
    size_t i4 = ((size_t)blockIdx.x * blockDim.x + threadIdx.x) * 4;
    float4 v = *reinterpret_cast<const float4*>(w + i4);
    __half2* o = reinterpret_cast<__half2*>(out + i4);
    o[0] = __floats2half2_rn(v.x, v.y);
    o[1] = __floats2half2_rn(v.z, v.w);
}

__global__ void rmsnorm_h(const float* __restrict__ x,
                          const float* __restrict__ g,
                          __half* __restrict__ out)
{
    int row = blockIdx.x, tid = threadIdx.x;
    float4 v = reinterpret_cast<const float4*>(x + (size_t)row * DQ)[tid];
    float s = v.x * v.x + v.y * v.y + v.z * v.z + v.w * v.w;
    #pragma unroll
    for (int o = 16; o > 0; o >>= 1) s += __shfl_xor_sync(0xFFFFFFFFu, s, o);
    __shared__ float red[8];
    __shared__ float scale_s;
    if ((tid & 31) == 0) red[tid >> 5] = s;
    __syncthreads();
    if (tid == 0) {
        float tt = 0.f;
        #pragma unroll
        for (int i = 0; i < 8; i++) tt += red[i];
        scale_s = rsqrtf(tt * (1.0f / DQ) + 1e-6f);
    }
    __syncthreads();
    float sc = scale_s;
    float4 gg = reinterpret_cast<const float4*>(g)[tid];
    __half2* o2 = reinterpret_cast<__half2*>(out + (size_t)row * DQ) + tid * 2;
    o2[0] = __floats2half2_rn(v.x * sc * gg.x, v.y * sc * gg.y);
    o2[1] = __floats2half2_rn(v.z * sc * gg.z, v.w * sc * gg.w);
}

// gates computed inline from flin/ilin
__device__ __forceinline__ void gate_eval(float fl, float il, float decay,
                                          float& f, float& z)
{
    float rem = decay / (1.0f + expf(-fl));
    f = 1.0f - rem;
    z = tanhf(il) * rem;
}

// chunked scan: 16 chunks x 256 steps; gate fused
__global__ void scan_p1(const float* __restrict__ flin, const float* __restrict__ ilin,
                        float* __restrict__ sA, float* __restrict__ sB)
{
    int tg = blockIdx.x * blockDim.x + threadIdx.x;
    int chunk = tg >> 13, c = tg & 8191;
    int b = c >> 11, hh = c & (HQ - 1);
    float decay = (float)hh * (1.0f / (float)(HQ - 1));
    size_t base = ((size_t)b * LQ + chunk * 256) * HQ + hh;
    float Aa = 1.f, Bb = 0.f;
    #pragma unroll 4
    for (int t = 0; t < 256; t++) {
        size_t i = base + (size_t)t * HQ;
        float f, z;
        gate_eval(flin[i], ilin[i], decay, f, z);
        Bb = fmaf(f, Bb, z);
        Aa *= f;
    }
    sA[tg] = Aa; sB[tg] = Bb;
}

__global__ void scan_p2(const float* __restrict__ h0,
                        const float* __restrict__ sA, const float* __restrict__ sB,
                        float* __restrict__ sS, float* __restrict__ hlast)
{
    int c = blockIdx.x * blockDim.x + threadIdx.x;
    float h = h0[c];
    #pragma unroll
    for (int k = 0; k < 16; k++) {
        sS[k * 8192 + c] = h;
        h = fmaf(sA[k * 8192 + c], h, sB[k * 8192 + c]);
    }
    hlast[c] = h;
}

__global__ void scan_p3(const float* __restrict__ flin, const float* __restrict__ ilin,
                        const float* __restrict__ sS, __half* __restrict__ out)
{
    int tg = blockIdx.x * blockDim.x + threadIdx.x;
    int chunk = tg >> 13, c = tg & 8191;
    int b = c >> 11, hh = c & (HQ - 1);
    float decay = (float)hh * (1.0f / (float)(HQ - 1));
    size_t base = ((size_t)b * LQ + chunk * 256) * HQ + hh;
    float h = sS[tg];
    #pragma unroll 2
    for (int t = 0; t < 256; t++) {
        size_t i = base + (size_t)t * HQ;
        float f, z;
        gate_eval(flin[i], ilin[i], decay, f, z);
        h = fmaf(f, h, z);
        out[i] = __float2half_rn(h);
    }
}

__global__ void swiglu_h(const float* __restrict__ u, const float* __restrict__ v,
                         __half* __restrict__ ff)
{
    size_t i4 = ((size_t)blockIdx.x * blockDim.x + threadIdx.x) * 4;
    float4 uu = *reinterpret_cast<const float4*>(u + i4);
    float4 vv = *reinterpret_cast<const float4*>(v + i4);
    float a = uu.x * vv.x / (1.0f + expf(-vv.x));
    float b = uu.y * vv.y / (1.0f + expf(-vv.y));
    float c = uu.z * vv.z / (1.0f + expf(-vv.z));
    float d = uu.w * vv.w / (1.0f + expf(-vv.w));
    __half2* o = reinterpret_cast<__half2*>(ff + i4);
    o[0] = __floats2half2_rn(a, b);
    o[1] = __floats2half2_rn(c, d);
}

// ---------------- launch ----------------
extern "C" void kernel_launch(void* const* d_in, const int* in_sizes, int n_in,
                              void* d_out, int out_size)
{
    const float* x      = (const float*)d_in[0];
    const float* hidden = (const float*)d_in[1];
    const float* w_f    = (const float*)d_in[2];
    const float* b_f    = (const float*)d_in[3];
    const float* w_i    = (const float*)d_in[4];
    const float* b_i    = (const float*)d_in[5];
    const float* w_ho   = (const float*)d_in[6];
    const float* b_ho   = (const float*)d_in[7];
    const float* w_fc   = (const float*)d_in[8];
    const float* b_fc   = (const float*)d_in[9];
    const float* w_fa   = (const float*)d_in[10];
    const float* b_fa   = (const float*)d_in[11];
    const float* w_fo   = (const float*)d_in[12];
    const float* b_fo   = (const float*)d_in[13];
    const float* g1     = (const float*)d_in[14];
    const float* g2     = (const float*)d_in[15];

    float* out_main  = (float*)d_out;
    float* out_hlast = out_main + (size_t)BLQ * DQ;

    __half *xnh, *hh, *wh;
    float *b1, *b2, *x1, *sA, *sB, *sS;
    cudaGetSymbolAddress((void**)&xnh, g_xnh);
    cudaGetSymbolAddress((void**)&hh,  g_hh);
    cudaGetSymbolAddress((void**)&wh,  g_wh);
    cudaGetSymbolAddress((void**)&b1,  g_b1);
    cudaGetSymbolAddress((void**)&b2,  g_b2);
    cudaGetSymbolAddress((void**)&x1,  g_x1);
    cudaGetSymbolAddress((void**)&sA,  g_sA);
    cudaGetSymbolAddress((void**)&sB,  g_sB);
    cudaGetSymbolAddress((void**)&sS,  g_sS);

    const size_t WSL = (size_t)HQ * DQ;           // 2M elems per weight
    __half* whf  = wh + 0 * WSL;
    __half* whi  = wh + 1 * WSL;
    __half* whho = wh + 2 * WSL;
    __half* whfc = wh + 3 * WSL;
    __half* whfa = wh + 4 * WSL;
    __half* whfo = wh + 5 * WSL;

    cudaFuncSetAttribute(gemm_h, cudaFuncAttributeMaxDynamicSharedMemorySize, GEMM_SMEM);

    int wcg = (int)(WSL / 4 / 256);               // 2048 blocks
    wconv<<<wcg, 256>>>(w_f,  whf);
    wconv<<<wcg, 256>>>(w_i,  whi);
    wconv<<<wcg, 256>>>(w_ho, whho);
    wconv<<<wcg, 256>>>(w_fc, whfc);
    wconv<<<wcg, 256>>>(w_fa, whfa);
    wconv<<<wcg, 256>>>(w_fo, whfo);

    dim3 gDH(HQ / BN, BLQ / BM);   // (16, 64)
    dim3 gHD(DQ / BN, BLQ / BM);   // (8, 64)

    rmsnorm_h<<<BLQ, 256>>>(x, g1, xnh);
    gemm_h<<<gDH, 256, GEMM_SMEM>>>(xnh, DQ, whf, b_f, nullptr, b1, HQ);
    gemm_h<<<gDH, 256, GEMM_SMEM>>>(xnh, DQ, whi, b_i, nullptr, b2, HQ);
    scan_p1<<<512, 256>>>(b1, b2, sA, sB);
    scan_p2<<<32, 256>>>(hidden, sA, sB, sS, out_hlast);
    scan_p3<<<512, 256>>>(b1, b2, sS, hh);
    gemm_h<<<gHD, 256, GEMM_SMEM>>>(hh, HQ, whho, b_ho, x, x1, DQ);
    rmsnorm_h<<<BLQ, 256>>>(x1, g2, xnh);
    gemm_h<<<gDH, 256, GEMM_SMEM>>>(xnh, DQ, whfc, b_fc, nullptr, b1, HQ);
    gemm_h<<<gDH, 256, GEMM_SMEM>>>(xnh, DQ, whfa, b_fa, nullptr, b2, HQ);
    swiglu_h<<<(BLQ * HQ) / 4 / 256, 256>>>(b1, b2, hh);
    gemm_h<<<gHD, 256, GEMM_SMEM>>>(hh, HQ, whfo, b_fo, x1, out_main, DQ);
}

// round 13
// speedup vs baseline: 7.4105x; 1.1757x over previous
#include <cuda_runtime.h>
#include <cuda_fp16.h>
#include <math.h>
#include <stdint.h>

#define BQ 4
#define LQ 4096
#define DQ 1024
#define HQ 2048
#define BLQ 16384

#define BM 256
#define BN 128
#define BKH 64
#define NST 4
#define A_STAGE 32768
#define B_STAGE 16384
#define STAGE_B (A_STAGE + B_STAGE)
#define GEMM_SMEM (NST * STAGE_B)   // 196608

// Scratch
__device__ __half  g_xnh[(size_t)BLQ * DQ];
__device__ __half  g_hh [(size_t)BLQ * HQ];          // h, then ff
__device__ __half  g_wh [6 * (size_t)HQ * DQ];       // wpfi(2), wpfcfa(2), whho(1), whfo(1)
__device__ __half2 g_rz [(size_t)BLQ * HQ];
__device__ float g_x1[(size_t)BLQ * DQ];
__device__ float g_sA[16 * 8192];
__device__ float g_sB[16 * 8192];
__device__ float g_sS[16 * 8192];

__device__ __forceinline__ void cp_async16(uint32_t saddr, const void* gptr) {
    asm volatile("cp.async.cg.shared.global [%0], [%1], 16;" :: "r"(saddr), "l"(gptr));
}
__device__ __forceinline__ void cp_commit() {
    asm volatile("cp.async.commit_group;" ::: "memory");
}
template <int N>
__device__ __forceinline__ void cp_wait() {
    asm volatile("cp.async.wait_group %0;" :: "n"(N) : "memory");
}
__device__ __forceinline__ uint32_t smem_u32(const void* p) {
    uint32_t a;
    asm("{ .reg .u64 t; cvta.to.shared.u64 t, %1; cvt.u32.u64 %0, t; }"
        : "=r"(a) : "l"(p));
    return a;
}
__device__ __forceinline__ void ldsm_x4(uint32_t* r, uint32_t addr) {
    asm volatile("ldmatrix.sync.aligned.m8n8.x4.shared.b16 {%0,%1,%2,%3}, [%4];"
        : "=r"(r[0]), "=r"(r[1]), "=r"(r[2]), "=r"(r[3]) : "r"(addr));
}
__device__ __forceinline__ void mma_f16(float* c, const uint32_t* a, const uint32_t* b) {
    asm volatile(
        "mma.sync.aligned.m16n8k16.row.col.f32.f16.f16.f32 "
        "{%0,%1,%2,%3}, {%4,%5,%6,%7}, {%8,%9}, {%0,%1,%2,%3};"
        : "+f"(c[0]), "+f"(c[1]), "+f"(c[2]), "+f"(c[3])
        : "r"(a[0]), "r"(a[1]), "r"(a[2]), "r"(a[3]), "r"(b[0]), "r"(b[1]));
}
#define SWZ(o) ((o) ^ (((o) >> 3) & 0x70))

// ---------------------------------------------------------------------------
// fp16 mma GEMM with fused epilogues.
// MODE 0: C(f32)[M,N] = A@W^T + bias0 (+resid)
// MODE 1: interleaved gate pair -> __half2(rem, z) at [M, HQ]
// MODE 2: interleaved swiglu pair -> __half ff at [M, HQ]
// Grid (Ncols/128, M/256), 256 threads, warp tile 64x64.
// ---------------------------------------------------------------------------
template <int MODE>
__global__ __launch_bounds__(256, 1)
void gemm_h(const __half* __restrict__ A, int K,
            const __half* __restrict__ W,
            const float* __restrict__ bias0,
            const float* __restrict__ bias1,
            const float* __restrict__ resid,
            void* __restrict__ outp, int N)
{
    extern __shared__ char sm[];
    int tid = threadIdx.x;
    int wid = tid >> 5, lane = tid & 31;
    int wm = wid >> 1, wn = wid & 1;
    int m0 = blockIdx.y * BM, n0 = blockIdx.x * BN;
    int nk = K / BKH;
    uint32_t sbase = smem_u32(sm);

    float acc[4][8][4];
    #pragma unroll
    for (int i = 0; i < 4; i++)
        #pragma unroll
        for (int j = 0; j < 8; j++)
            #pragma unroll
            for (int r = 0; r < 4; r++) acc[i][j][r] = 0.f;

    auto load_stage = [&](int s, int kc) {
        uint32_t sa = sbase + s * STAGE_B;
        int kb = kc * BKH;
        #pragma unroll
        for (int i = 0; i < 8; i++) {
            int idx = i * 256 + tid;
            int row = idx >> 3, c8 = idx & 7;
            cp_async16(sa + SWZ(row * 128 + c8 * 16),
                       A + (size_t)(m0 + row) * K + kb + c8 * 8);
        }
        #pragma unroll
        for (int i = 0; i < 4; i++) {
            int idx = i * 256 + tid;
            int row = idx >> 3, c8 = idx & 7;
            cp_async16(sa + A_STAGE + SWZ(row * 128 + c8 * 16),
                       W + (size_t)(n0 + row) * K + kb + c8 * 8);
        }
        cp_commit();
    };

    #pragma unroll
    for (int s = 0; s < NST - 1; s++) load_stage(s, s);

    for (int k0 = 0; k0 < nk; k0++) {
        cp_wait<NST - 2>();
        __syncthreads();
        if (k0 + NST - 1 < nk) load_stage((k0 + NST - 1) % NST, k0 + NST - 1);

        uint32_t saA = sbase + (k0 % NST) * STAGE_B;
        uint32_t saB = saA + A_STAGE;

        #pragma unroll
        for (int kk = 0; kk < 4; kk++) {
            int kc = kk * 16;
            uint32_t af[4][4], bf[8][2];
            #pragma unroll
            for (int mt = 0; mt < 4; mt++) {
                int row = wm * 64 + mt * 16 + (lane & 15);
                int colh = kc + ((lane >> 4) << 3);
                ldsm_x4(af[mt], saA + SWZ(row * 128 + colh * 2));
            }
            #pragma unroll
            for (int np = 0; np < 4; np++) {
                uint32_t r[4];
                int n = wn * 64 + np * 16 + (lane & 7) + ((lane >> 4) << 3);
                int colh = kc + (((lane >> 3) & 1) << 3);
                ldsm_x4(r, saB + SWZ(n * 128 + colh * 2));
                bf[np * 2 + 0][0] = r[0]; bf[np * 2 + 0][1] = r[1];
                bf[np * 2 + 1][0] = r[2]; bf[np * 2 + 1][1] = r[3];
            }
            #pragma unroll
            for (int mt = 0; mt < 4; mt++)
                #pragma unroll
                for (int nt = 0; nt < 8; nt++)
                    mma_f16(acc[mt][nt], af[mt], bf[nt]);
        }
        __syncthreads();
    }

    int g = lane >> 2, t = lane & 3;
    #pragma unroll
    for (int mt = 0; mt < 4; mt++) {
        #pragma unroll
        for (int nt = 0; nt < 8; nt++) {
            int col = n0 + wn * 64 + nt * 8 + 2 * t;
            int row = m0 + wm * 64 + mt * 16 + g;
            if (MODE == 0) {
                float2 b2 = *reinterpret_cast<const float2*>(&bias0[col]);
                #pragma unroll
                for (int hr = 0; hr < 2; hr++) {
                    size_t off = (size_t)(row + hr * 8) * N + col;
                    float2 v;
                    v.x = acc[mt][nt][hr * 2 + 0] + b2.x;
                    v.y = acc[mt][nt][hr * 2 + 1] + b2.y;
                    if (resid) {
                        float2 q = *reinterpret_cast<const float2*>(&resid[off]);
                        v.x += q.x; v.y += q.y;
                    }
                    *reinterpret_cast<float2*>(&((float*)outp)[off]) = v;
                }
            } else {
                int h = col >> 1;
                float bf0 = bias0[h], bf1 = bias1[h];
                #pragma unroll
                for (int hr = 0; hr < 2; hr++) {
                    size_t off = (size_t)(row + hr * 8) * HQ + h;
                    float c0 = acc[mt][nt][hr * 2 + 0] + bf0;
                    float c1 = acc[mt][nt][hr * 2 + 1] + bf1;
                    if (MODE == 1) {
                        float decay = (float)h * (1.0f / (float)(HQ - 1));
                        float rem = decay / (1.0f + expf(-c0));
                        float z = tanhf(c1) * rem;
                        ((__half2*)outp)[off] = __floats2half2_rn(rem, z);
                    } else {
                        float ff = c0 * c1 / (1.0f + expf(-c1));
                        ((__half*)outp)[off] = __float2half_rn(ff);
                    }
                }
            }
        }
    }
}

// ---------------- conversions / elementwise ----------------
__global__ void wconv(const float* __restrict__ w, __half* __restrict__ out)
{
    size_t i4 = ((size_t)blockIdx.x * blockDim.x + threadIdx.x) * 4;
    float4 v = *reinterpret_cast<const float4*>(w + i4);
    __half2* o = reinterpret_cast<__half2*>(out + i4);
    o[0] = __floats2half2_rn(v.x, v.y);
    o[1] = __floats2half2_rn(v.z, v.w);
}

// interleave rows: out[2j] = a[j], out[2j+1] = b[j]  (K = DQ)
__global__ void wconv_pair(const float* __restrict__ a, const float* __restrict__ b,
                           __half* __restrict__ out)
{
    size_t i4 = ((size_t)blockIdx.x * blockDim.x + threadIdx.x) * 4;
    int j = (int)(i4 >> 10);
    int k = (int)(i4 & (DQ - 1));
    float4 va = *reinterpret_cast<const float4*>(a + i4);
    float4 vb = *reinterpret_cast<const float4*>(b + i4);
    __half2* oa = reinterpret_cast<__half2*>(out + ((size_t)(2 * j) * DQ + k));
    __half2* ob = reinterpret_cast<__half2*>(out + ((size_t)(2 * j + 1) * DQ + k));
    oa[0] = __floats2half2_rn(va.x, va.y);
    oa[1] = __floats2half2_rn(va.z, va.w);
    ob[0] = __floats2half2_rn(vb.x, vb.y);
    ob[1] = __floats2half2_rn(vb.z, vb.w);
}

__global__ void rmsnorm_h(const float* __restrict__ x,
                          const float* __restrict__ g,
                          __half* __restrict__ out)
{
    int row = blockIdx.x, tid = threadIdx.x;
    float4 v = reinterpret_cast<const float4*>(x + (size_t)row * DQ)[tid];
    float s = v.x * v.x + v.y * v.y + v.z * v.z + v.w * v.w;
    #pragma unroll
    for (int o = 16; o > 0; o >>= 1) s += __shfl_xor_sync(0xFFFFFFFFu, s, o);
    __shared__ float red[8];
    __shared__ float scale_s;
    if ((tid & 31) == 0) red[tid >> 5] = s;
    __syncthreads();
    if (tid == 0) {
        float tt = 0.f;
        #pragma unroll
        for (int i = 0; i < 8; i++) tt += red[i];
        scale_s = rsqrtf(tt * (1.0f / DQ) + 1e-6f);
    }
    __syncthreads();
    float sc = scale_s;
    float4 gg = reinterpret_cast<const float4*>(g)[tid];
    __half2* o2 = reinterpret_cast<__half2*>(out + (size_t)row * DQ) + tid * 2;
    o2[0] = __floats2half2_rn(v.x * sc * gg.x, v.y * sc * gg.y);
    o2[1] = __floats2half2_rn(v.z * sc * gg.z, v.w * sc * gg.w);
}

// chunked scan over precomputed __half2(rem, z): 16 chunks x 256 steps
__global__ void scan_p1(const __half2* __restrict__ rz,
                        float* __restrict__ sA, float* __restrict__ sB)
{
    int tg = blockIdx.x * blockDim.x + threadIdx.x;
    int chunk = tg >> 13, c = tg & 8191;
    int b = c >> 11, hh = c & (HQ - 1);
    size_t base = ((size_t)b * LQ + chunk * 256) * HQ + hh;
    float Aa = 1.f, Bb = 0.f;
    #pragma unroll 4
    for (int t = 0; t < 256; t++) {
        float2 v = __half22float2(rz[base + (size_t)t * HQ]);
        float f = 1.0f - v.x;
        Bb = fmaf(f, Bb, v.y);
        Aa *= f;
    }
    sA[tg] = Aa; sB[tg] = Bb;
}

__global__ void scan_p2(const float* __restrict__ h0,
                        const float* __restrict__ sA, const float* __restrict__ sB,
                        float* __restrict__ sS, float* __restrict__ hlast)
{
    int c = blockIdx.x * blockDim.x + threadIdx.x;
    float h = h0[c];
    #pragma unroll
    for (int k = 0; k < 16; k++) {
        sS[k * 8192 + c] = h;
        h = fmaf(sA[k * 8192 + c], h, sB[k * 8192 + c]);
    }
    hlast[c] = h;
}

__global__ void scan_p3(const __half2* __restrict__ rz,
                        const float* __restrict__ sS, __half* __restrict__ out)
{
    int tg = blockIdx.x * blockDim.x + threadIdx.x;
    int chunk = tg >> 13, c = tg & 8191;
    int b = c >> 11, hh = c & (HQ - 1);
    size_t base = ((size_t)b * LQ + chunk * 256) * HQ + hh;
    float h = sS[tg];
    #pragma unroll 4
    for (int t = 0; t < 256; t++) {
        size_t i = base + (size_t)t * HQ;
        float2 v = __half22float2(rz[i]);
        h = fmaf(1.0f - v.x, h, v.y);
        out[i] = __float2half_rn(h);
    }
}

// ---------------- launch ----------------
extern "C" void kernel_launch(void* const* d_in, const int* in_sizes, int n_in,
                              void* d_out, int out_size)
{
    const float* x      = (const float*)d_in[0];
    const float* hidden = (const float*)d_in[1];
    const float* w_f    = (const float*)d_in[2];
    const float* b_f    = (const float*)d_in[3];
    const float* w_i    = (const float*)d_in[4];
    const float* b_i    = (const float*)d_in[5];
    const float* w_ho   = (const float*)d_in[6];
    const float* b_ho   = (const float*)d_in[7];
    const float* w_fc   = (const float*)d_in[8];
    const float* b_fc   = (const float*)d_in[9];
    const float* w_fa   = (const float*)d_in[10];
    const float* b_fa   = (const float*)d_in[11];
    const float* w_fo   = (const float*)d_in[12];
    const float* b_fo   = (const float*)d_in[13];
    const float* g1     = (const float*)d_in[14];
    const float* g2     = (const float*)d_in[15];

    float* out_main  = (float*)d_out;
    float* out_hlast = out_main + (size_t)BLQ * DQ;

    __half *xnh, *hh, *wh;
    __half2* rz;
    float *x1, *sA, *sB, *sS;
    cudaGetSymbolAddress((void**)&xnh, g_xnh);
    cudaGetSymbolAddress((void**)&hh,  g_hh);
    cudaGetSymbolAddress((void**)&wh,  g_wh);
    cudaGetSymbolAddress((void**)&rz,  g_rz);
    cudaGetSymbolAddress((void**)&x1,  g_x1);
    cudaGetSymbolAddress((void**)&sA,  g_sA);
    cudaGetSymbolAddress((void**)&sB,  g_sB);
    cudaGetSymbolAddress((void**)&sS,  g_sS);

    const size_t WSL = (size_t)HQ * DQ;   // 2M halves
    __half* wpfi   = wh + 0 * WSL;        // interleaved [4096,1024] -> 2 slots
    __half* wpfcfa = wh + 2 * WSL;        // interleaved [4096,1024] -> 2 slots
    __half* whho   = wh + 4 * WSL;        // [1024,2048] -> 1 slot
    __half* whfo   = wh + 5 * WSL;        // [1024,2048] -> 1 slot

    cudaFuncSetAttribute(gemm_h<0>, cudaFuncAttributeMaxDynamicSharedMemorySize, GEMM_SMEM);
    cudaFuncSetAttribute(gemm_h<1>, cudaFuncAttributeMaxDynamicSharedMemorySize, GEMM_SMEM);
    cudaFuncSetAttribute(gemm_h<2>, cudaFuncAttributeMaxDynamicSharedMemorySize, GEMM_SMEM);

    int wcg = (int)(WSL / 4 / 256);
    wconv_pair<<<wcg, 256>>>(w_f, w_i, wpfi);
    wconv_pair<<<wcg, 256>>>(w_fc, w_fa, wpfcfa);
    wconv<<<wcg, 256>>>(w_ho, whho);
    wconv<<<wcg, 256>>>(w_fo, whfo);

    dim3 gPair(2 * HQ / BN, BLQ / BM);   // (32, 64)
    dim3 gHD(DQ / BN, BLQ / BM);         // (8, 64)

    rmsnorm_h<<<BLQ, 256>>>(x, g1, xnh);
    gemm_h<1><<<gPair, 256, GEMM_SMEM>>>(xnh, DQ, wpfi, b_f, b_i, nullptr, rz, HQ);
    scan_p1<<<512, 256>>>(rz, sA, sB);
    scan_p2<<<32, 256>>>(hidden, sA, sB, sS, out_hlast);
    scan_p3<<<512, 256>>>(rz, sS, hh);
    gemm_h<0><<<gHD, 256, GEMM_SMEM>>>(hh, HQ, whho, b_ho, nullptr, x, x1, DQ);
    rmsnorm_h<<<BLQ, 256>>>(x1, g2, xnh);
    gemm_h<2><<<gPair, 256, GEMM_SMEM>>>(xnh, DQ, wpfcfa, b_fc, b_fa, nullptr, hh, HQ);
    gemm_h<0><<<gHD, 256, GEMM_SMEM>>>(hh, HQ, whfo, b_fo, nullptr, x1, out_main, DQ);
}

// round 14
// speedup vs baseline: 8.1274x; 1.0967x over previous
#include <cuda_runtime.h>
#include <cuda_fp16.h>
#include <math.h>
#include <stdint.h>

#define BQ 4
#define LQ 4096
#define DQ 1024
#define HQ 2048
#define BLQ 16384

// Scratch
__device__ __half  g_xnh[(size_t)BLQ * DQ];
__device__ __half  g_hh [(size_t)BLQ * HQ];          // h, then ff
__device__ __half  g_wh [6 * (size_t)HQ * DQ];       // wpfi(2), wpfcfa(2), whho(1), whfo(1)
__device__ __half2 g_rz [(size_t)BLQ * HQ];
__device__ float g_x1[(size_t)BLQ * DQ];
__device__ float g_sA[16 * 8192];
__device__ float g_sB[16 * 8192];
__device__ float g_sS[16 * 8192];

__device__ __forceinline__ void cp_async16(uint32_t saddr, const void* gptr) {
    asm volatile("cp.async.cg.shared.global [%0], [%1], 16;" :: "r"(saddr), "l"(gptr));
}
__device__ __forceinline__ void cp_commit() {
    asm volatile("cp.async.commit_group;" ::: "memory");
}
template <int N>
__device__ __forceinline__ void cp_wait() {
    asm volatile("cp.async.wait_group %0;" :: "n"(N) : "memory");
}
__device__ __forceinline__ uint32_t smem_u32(const void* p) {
    uint32_t a;
    asm("{ .reg .u64 t; cvta.to.shared.u64 t, %1; cvt.u32.u64 %0, t; }"
        : "=r"(a) : "l"(p));
    return a;
}
__device__ __forceinline__ void ldsm_x4(uint32_t* r, uint32_t addr) {
    asm volatile("ldmatrix.sync.aligned.m8n8.x4.shared.b16 {%0,%1,%2,%3}, [%4];"
        : "=r"(r[0]), "=r"(r[1]), "=r"(r[2]), "=r"(r[3]) : "r"(addr));
}
__device__ __forceinline__ void mma_f16(float* c, const uint32_t* a, const uint32_t* b) {
    asm volatile(
        "mma.sync.aligned.m16n8k16.row.col.f32.f16.f16.f32 "
        "{%0,%1,%2,%3}, {%4,%5,%6,%7}, {%8,%9}, {%0,%1,%2,%3};"
        : "+f"(c[0]), "+f"(c[1]), "+f"(c[2]), "+f"(c[3])
        : "r"(a[0]), "r"(a[1]), "r"(a[2]), "r"(a[3]), "r"(b[0]), "r"(b[1]));
}
#define SWZ(o) ((o) ^ (((o) >> 3) & 0x70))

// ---------------------------------------------------------------------------
// fp16 mma GEMM with fused epilogues.
// MODE 0: C(f32)[M,N] = A@W^T + bias0 (+resid)
// MODE 1: interleaved gate pair -> __half2(rem, z) at [M, HQ]
// MODE 2: interleaved swiglu pair -> __half ff at [M, HQ]
// MT: m-tiles per warp (4 -> BM=256 @1CTA/SM, 2 -> BM=128 @2CTA/SM)
// NSTG: cp.async stages. BN=128 fixed, 256 threads, 4x2 warp grid.
// ---------------------------------------------------------------------------
template <int MODE, int MT, int NSTG>
__global__ __launch_bounds__(256, (MT == 2 ? 2 : 1))
void gemm_h(const __half* __restrict__ A, int K,
            const __half* __restrict__ W,
            const float* __restrict__ bias0,
            const float* __restrict__ bias1,
            const float* __restrict__ resid,
            void* __restrict__ outp, int N)
{
    constexpr int BMv = 64 * MT;
    constexpr int A_ST = BMv * 128;       // bytes
    constexpr int B_ST = 16384;
    constexpr int ST = A_ST + B_ST;

    extern __shared__ char sm[];
    int tid = threadIdx.x;
    int wid = tid >> 5, lane = tid & 31;
    int wm = wid >> 1, wn = wid & 1;
    int m0 = blockIdx.y * BMv, n0 = blockIdx.x * 128;
    int nk = K >> 6;
    uint32_t sbase = smem_u32(sm);

    float acc[MT][8][4];
    #pragma unroll
    for (int i = 0; i < MT; i++)
        #pragma unroll
        for (int j = 0; j < 8; j++)
            #pragma unroll
            for (int r = 0; r < 4; r++) acc[i][j][r] = 0.f;

    auto load_stage = [&](int s, int kc) {
        uint32_t sa = sbase + s * ST;
        int kb = kc * 64;
        #pragma unroll
        for (int i = 0; i < 2 * MT; i++) {
            int idx = i * 256 + tid;
            int row = idx >> 3, c8 = idx & 7;
            cp_async16(sa + SWZ(row * 128 + c8 * 16),
                       A + (size_t)(m0 + row) * K + kb + c8 * 8);
        }
        #pragma unroll
        for (int i = 0; i < 4; i++) {
            int idx = i * 256 + tid;
            int row = idx >> 3, c8 = idx & 7;
            cp_async16(sa + A_ST + SWZ(row * 128 + c8 * 16),
                       W + (size_t)(n0 + row) * K + kb + c8 * 8);
        }
        cp_commit();
    };

    #pragma unroll
    for (int s = 0; s < NSTG - 1; s++) load_stage(s, s);

    for (int k0 = 0; k0 < nk; k0++) {
        cp_wait<NSTG - 2>();
        __syncthreads();
        if (k0 + NSTG - 1 < nk) load_stage((k0 + NSTG - 1) % NSTG, k0 + NSTG - 1);

        uint32_t saA = sbase + (k0 % NSTG) * ST;
        uint32_t saB = saA + A_ST;

        #pragma unroll
        for (int kk = 0; kk < 4; kk++) {
            int kc = kk * 16;
            uint32_t af[MT][4], bf[8][2];
            #pragma unroll
            for (int mt = 0; mt < MT; mt++) {
                int row = wm * (16 * MT) + mt * 16 + (lane & 15);
                int colh = kc + ((lane >> 4) << 3);
                ldsm_x4(af[mt], saA + SWZ(row * 128 + colh * 2));
            }
            #pragma unroll
            for (int np = 0; np < 4; np++) {
                uint32_t r[4];
                int n = wn * 64 + np * 16 + (lane & 7) + ((lane >> 4) << 3);
                int colh = kc + (((lane >> 3) & 1) << 3);
                ldsm_x4(r, saB + SWZ(n * 128 + colh * 2));
                bf[np * 2 + 0][0] = r[0]; bf[np * 2 + 0][1] = r[1];
                bf[np * 2 + 1][0] = r[2]; bf[np * 2 + 1][1] = r[3];
            }
            #pragma unroll
            for (int mt = 0; mt < MT; mt++)
                #pragma unroll
                for (int nt = 0; nt < 8; nt++)
                    mma_f16(acc[mt][nt], af[mt], bf[nt]);
        }
        // NOTE: no trailing __syncthreads — the top-of-loop cp_wait+sync is the
        // only barrier needed (next-iter writes target a different stage).
    }

    int g = lane >> 2, t = lane & 3;
    #pragma unroll
    for (int mt = 0; mt < MT; mt++) {
        #pragma unroll
        for (int nt = 0; nt < 8; nt++) {
            int col = n0 + wn * 64 + nt * 8 + 2 * t;
            int row = m0 + wm * (16 * MT) + mt * 16 + g;
            if (MODE == 0) {
                float2 b2 = *reinterpret_cast<const float2*>(&bias0[col]);
                #pragma unroll
                for (int hr = 0; hr < 2; hr++) {
                    size_t off = (size_t)(row + hr * 8) * N + col;
                    float2 v;
                    v.x = acc[mt][nt][hr * 2 + 0] + b2.x;
                    v.y = acc[mt][nt][hr * 2 + 1] + b2.y;
                    if (resid) {
                        float2 q = *reinterpret_cast<const float2*>(&resid[off]);
                        v.x += q.x; v.y += q.y;
                    }
                    *reinterpret_cast<float2*>(&((float*)outp)[off]) = v;
                }
            } else {
                int h = col >> 1;
                float bf0 = bias0[h], bf1 = bias1[h];
                #pragma unroll
                for (int hr = 0; hr < 2; hr++) {
                    size_t off = (size_t)(row + hr * 8) * HQ + h;
                    float c0 = acc[mt][nt][hr * 2 + 0] + bf0;
                    float c1 = acc[mt][nt][hr * 2 + 1] + bf1;
                    if (MODE == 1) {
                        float decay = (float)h * (1.0f / (float)(HQ - 1));
                        float rem = decay / (1.0f + expf(-c0));
                        float z = tanhf(c1) * rem;
                        ((__half2*)outp)[off] = __floats2half2_rn(rem, z);
                    } else {
                        float ff = c0 * c1 / (1.0f + expf(-c1));
                        ((__half*)outp)[off] = __float2half_rn(ff);
                    }
                }
            }
        }
    }
}

// ---------------- conversions / elementwise ----------------
__global__ void wconv(const float* __restrict__ w, __half* __restrict__ out)
{
    size_t i4 = ((size_t)blockIdx.x * blockDim.x + threadIdx.x) * 4;
    float4 v = *reinterpret_cast<const float4*>(w + i4);
    __half2* o = reinterpret_cast<__half2*>(out + i4);
    o[0] = __floats2half2_rn(v.x, v.y);
    o[1] = __floats2half2_rn(v.z, v.w);
}

__global__ void wconv_pair(const float* __restrict__ a, const float* __restrict__ b,
                           __half* __restrict__ out)
{
    size_t i4 = ((size_t)blockIdx.x * blockDim.x + threadIdx.x) * 4;
    int j = (int)(i4 >> 10);
    int k = (int)(i4 & (DQ - 1));
    float4 va = *reinterpret_cast<const float4*>(a + i4);
    float4 vb = *reinterpret_cast<const float4*>(b + i4);
    __half2* oa = reinterpret_cast<__half2*>(out + ((size_t)(2 * j) * DQ + k));
    __half2* ob = reinterpret_cast<__half2*>(out + ((size_t)(2 * j + 1) * DQ + k));
    oa[0] = __floats2half2_rn(va.x, va.y);
    oa[1] = __floats2half2_rn(va.z, va.w);
    ob[0] = __floats2half2_rn(vb.x, vb.y);
    ob[1] = __floats2half2_rn(vb.z, vb.w);
}

__global__ void rmsnorm_h(const float* __restrict__ x,
                          const float* __restrict__ g,
                          __half* __restrict__ out)
{
    int row = blockIdx.x, tid = threadIdx.x;
    float4 v = reinterpret_cast<const float4*>(x + (size_t)row * DQ)[tid];
    float s = v.x * v.x + v.y * v.y + v.z * v.z + v.w * v.w;
    #pragma unroll
    for (int o = 16; o > 0; o >>= 1) s += __shfl_xor_sync(0xFFFFFFFFu, s, o);
    __shared__ float red[8];
    __shared__ float scale_s;
    if ((tid & 31) == 0) red[tid >> 5] = s;
    __syncthreads();
    if (tid == 0) {
        float tt = 0.f;
        #pragma unroll
        for (int i = 0; i < 8; i++) tt += red[i];
        scale_s = rsqrtf(tt * (1.0f / DQ) + 1e-6f);
    }
    __syncthreads();
    float sc = scale_s;
    float4 gg = reinterpret_cast<const float4*>(g)[tid];
    __half2* o2 = reinterpret_cast<__half2*>(out + (size_t)row * DQ) + tid * 2;
    o2[0] = __floats2half2_rn(v.x * sc * gg.x, v.y * sc * gg.y);
    o2[1] = __floats2half2_rn(v.z * sc * gg.z, v.w * sc * gg.w);
}

// chunked scan over precomputed __half2(rem, z): 16 chunks x 256 steps
__global__ void scan_p1(const __half2* __restrict__ rz,
                        float* __restrict__ sA, float* __restrict__ sB)
{
    int tg = blockIdx.x * blockDim.x + threadIdx.x;
    int chunk = tg >> 13, c = tg & 8191;
    int b = c >> 11, hh = c & (HQ - 1);
    size_t base = ((size_t)b * LQ + chunk * 256) * HQ + hh;
    float Aa = 1.f, Bb = 0.f;
    #pragma unroll 4
    for (int t = 0; t < 256; t++) {
        float2 v = __half22float2(rz[base + (size_t)t * HQ]);
        float f = 1.0f - v.x;
        Bb = fmaf(f, Bb, v.y);
        Aa *= f;
    }
    sA[tg] = Aa; sB[tg] = Bb;
}

__global__ void scan_p2(const float* __restrict__ h0,
                        const float* __restrict__ sA, const float* __restrict__ sB,
                        float* __restrict__ sS, float* __restrict__ hlast)
{
    int c = blockIdx.x * blockDim.x + threadIdx.x;
    float h = h0[c];
    #pragma unroll
    for (int k = 0; k < 16; k++) {
        sS[k * 8192 + c] = h;
        h = fmaf(sA[k * 8192 + c], h, sB[k * 8192 + c]);
    }
    hlast[c] = h;
}

__global__ void scan_p3(const __half2* __restrict__ rz,
                        const float* __restrict__ sS, __half* __restrict__ out)
{
    int tg = blockIdx.x * blockDim.x + threadIdx.x;
    int chunk = tg >> 13, c = tg & 8191;
    int b = c >> 11, hh = c & (HQ - 1);
    size_t base = ((size_t)b * LQ + chunk * 256) * HQ + hh;
    float h = sS[tg];
    #pragma unroll 4
    for (int t = 0; t < 256; t++) {
        size_t i = base + (size_t)t * HQ;
        float2 v = __half22float2(rz[i]);
        h = fmaf(1.0f - v.x, h, v.y);
        out[i] = __float2half_rn(h);
    }
}

// ---------------- launch ----------------
extern "C" void kernel_launch(void* const* d_in, const int* in_sizes, int n_in,
                              void* d_out, int out_size)
{
    const float* x      = (const float*)d_in[0];
    const float* hidden = (const float*)d_in[1];
    const float* w_f    = (const float*)d_in[2];
    const float* b_f    = (const float*)d_in[3];
    const float* w_i    = (const float*)d_in[4];
    const float* b_i    = (const float*)d_in[5];
    const float* w_ho   = (const float*)d_in[6];
    const float* b_ho   = (const float*)d_in[7];
    const float* w_fc   = (const float*)d_in[8];
    const float* b_fc   = (const float*)d_in[9];
    const float* w_fa   = (const float*)d_in[10];
    const float* b_fa   = (const float*)d_in[11];
    const float* w_fo   = (const float*)d_in[12];
    const float* b_fo   = (const float*)d_in[13];
    const float* g1     = (const float*)d_in[14];
    const float* g2     = (const float*)d_in[15];

    float* out_main  = (float*)d_out;
    float* out_hlast = out_main + (size_t)BLQ * DQ;

    __half *xnh, *hh, *wh;
    __half2* rz;
    float *x1, *sA, *sB, *sS;
    cudaGetSymbolAddress((void**)&xnh, g_xnh);
    cudaGetSymbolAddress((void**)&hh,  g_hh);
    cudaGetSymbolAddress((void**)&wh,  g_wh);
    cudaGetSymbolAddress((void**)&rz,  g_rz);
    cudaGetSymbolAddress((void**)&x1,  g_x1);
    cudaGetSymbolAddress((void**)&sA,  g_sA);
    cudaGetSymbolAddress((void**)&sB,  g_sB);
    cudaGetSymbolAddress((void**)&sS,  g_sS);

    const size_t WSL = (size_t)HQ * DQ;   // 2M halves
    __half* wpfi   = wh + 0 * WSL;        // interleaved [4096,1024]
    __half* wpfcfa = wh + 2 * WSL;        // interleaved [4096,1024]
    __half* whho   = wh + 4 * WSL;        // [1024,2048]
    __half* whfo   = wh + 5 * WSL;        // [1024,2048]

    // smem sizes: pair config MT=4,NST=4 -> 4*(32768+16384)=196608
    //             HD   config MT=2,NST=3 -> 3*(16384+16384)=98304 (2 CTAs/SM)
    const int SMEM_PAIR = 4 * (32768 + 16384);
    const int SMEM_HD   = 3 * (16384 + 16384);

    cudaFuncSetAttribute(gemm_h<1,4,4>, cudaFuncAttributeMaxDynamicSharedMemorySize, SMEM_PAIR);
    cudaFuncSetAttribute(gemm_h<2,4,4>, cudaFuncAttributeMaxDynamicSharedMemorySize, SMEM_PAIR);
    cudaFuncSetAttribute(gemm_h<0,2,3>, cudaFuncAttributeMaxDynamicSharedMemorySize, SMEM_HD);

    int wcg = (int)(WSL / 4 / 256);
    wconv_pair<<<wcg, 256>>>(w_f, w_i, wpfi);
    wconv_pair<<<wcg, 256>>>(w_fc, w_fa, wpfcfa);
    wconv<<<wcg, 256>>>(w_ho, whho);
    wconv<<<wcg, 256>>>(w_fo, whfo);

    dim3 gPair(2 * HQ / 128, BLQ / 256);   // (32, 64)
    dim3 gHD(DQ / 128, BLQ / 128);         // (8, 128)

    rmsnorm_h<<<BLQ, 256>>>(x, g1, xnh);
    gemm_h<1,4,4><<<gPair, 256, SMEM_PAIR>>>(xnh, DQ, wpfi, b_f, b_i, nullptr, rz, HQ);
    scan_p1<<<512, 256>>>(rz, sA, sB);
    scan_p2<<<32, 256>>>(hidden, sA, sB, sS, out_hlast);
    scan_p3<<<512, 256>>>(rz, sS, hh);
    gemm_h<0,2,3><<<gHD, 256, SMEM_HD>>>(hh, HQ, whho, b_ho, nullptr, x, x1, DQ);
    rmsnorm_h<<<BLQ, 256>>>(x1, g2, xnh);
    gemm_h<2,4,4><<<gPair, 256, SMEM_PAIR>>>(xnh, DQ, wpfcfa, b_fc, b_fa, nullptr, hh, HQ);
    gemm_h<0,2,3><<<gHD, 256, SMEM_HD>>>(hh, HQ, whfo, b_fo, nullptr, x1, out_main, DQ);
}

// round 15
// speedup vs baseline: 8.3732x; 1.0302x over previous
#include <cuda_runtime.h>
#include <cuda_fp16.h>
#include <math.h>
#include <stdint.h>

#define BQ 4
#define LQ 4096
#define DQ 1024
#define HQ 2048
#define BLQ 16384

// Scratch
__device__ __half  g_xnh[(size_t)BLQ * DQ];
__device__ __half  g_hh [(size_t)BLQ * HQ];          // h, then ff
__device__ __half  g_wh [6 * (size_t)HQ * DQ];       // wpfi(2), wpfcfa(2), whho(1), whfo(1)
__device__ __half2 g_rz [(size_t)BLQ * HQ];
__device__ float g_x1[(size_t)BLQ * DQ];
__device__ float g_sA[16 * 8192];
__device__ float g_sB[16 * 8192];
__device__ float g_sS[16 * 8192];

__device__ __forceinline__ void cp_async16(uint32_t saddr, const void* gptr) {
    asm volatile("cp.async.cg.shared.global [%0], [%1], 16;" :: "r"(saddr), "l"(gptr));
}
__device__ __forceinline__ void cp_commit() {
    asm volatile("cp.async.commit_group;" ::: "memory");
}
template <int N>
__device__ __forceinline__ void cp_wait() {
    asm volatile("cp.async.wait_group %0;" :: "n"(N) : "memory");
}
__device__ __forceinline__ uint32_t smem_u32(const void* p) {
    uint32_t a;
    asm("{ .reg .u64 t; cvta.to.shared.u64 t, %1; cvt.u32.u64 %0, t; }"
        : "=r"(a) : "l"(p));
    return a;
}
__device__ __forceinline__ void ldsm_x4(uint32_t* r, uint32_t addr) {
    asm volatile("ldmatrix.sync.aligned.m8n8.x4.shared.b16 {%0,%1,%2,%3}, [%4];"
        : "=r"(r[0]), "=r"(r[1]), "=r"(r[2]), "=r"(r[3]) : "r"(addr));
}
__device__ __forceinline__ void mma_f16(float* c, const uint32_t* a, const uint32_t* b) {
    asm volatile(
        "mma.sync.aligned.m16n8k16.row.col.f32.f16.f16.f32 "
        "{%0,%1,%2,%3}, {%4,%5,%6,%7}, {%8,%9}, {%0,%1,%2,%3};"
        : "+f"(c[0]), "+f"(c[1]), "+f"(c[2]), "+f"(c[3])
        : "r"(a[0]), "r"(a[1]), "r"(a[2]), "r"(a[3]), "r"(b[0]), "r"(b[1]));
}
#define SWZ(o) ((o) ^ (((o) >> 3) & 0x70))

// ---------------------------------------------------------------------------
// fp16 mma GEMM with fused epilogues.
// MODE 0: C(f32)[M,N] = A@W^T + bias0 (+resid)
// MODE 1: interleaved gate pair -> __half2(rem, z) at [M, HQ]
// MODE 2: interleaved swiglu pair -> __half ff at [M, HQ]
// MT: m-tiles per warp (2 -> BM=128 @2CTA/SM). NSTG: cp.async stages.
// BN=128 fixed, 256 threads, 4x2 warp grid.
// ---------------------------------------------------------------------------
template <int MODE, int MT, int NSTG>
__global__ __launch_bounds__(256, (MT == 2 ? 2 : 1))
void gemm_h(const __half* __restrict__ A, int K,
            const __half* __restrict__ W,
            const float* __restrict__ bias0,
            const float* __restrict__ bias1,
            const float* __restrict__ resid,
            void* __restrict__ outp, int N)
{
    constexpr int BMv = 64 * MT;
    constexpr int A_ST = BMv * 128;       // bytes
    constexpr int B_ST = 16384;
    constexpr int ST = A_ST + B_ST;

    extern __shared__ char sm[];
    int tid = threadIdx.x;
    int wid = tid >> 5, lane = tid & 31;
    int wm = wid >> 1, wn = wid & 1;
    int m0 = blockIdx.y * BMv, n0 = blockIdx.x * 128;
    int nk = K >> 6;
    uint32_t sbase = smem_u32(sm);

    float acc[MT][8][4];
    #pragma unroll
    for (int i = 0; i < MT; i++)
        #pragma unroll
        for (int j = 0; j < 8; j++)
            #pragma unroll
            for (int r = 0; r < 4; r++) acc[i][j][r] = 0.f;

    auto load_stage = [&](int s, int kc) {
        uint32_t sa = sbase + s * ST;
        int kb = kc * 64;
        #pragma unroll
        for (int i = 0; i < 2 * MT; i++) {
            int idx = i * 256 + tid;
            int row = idx >> 3, c8 = idx & 7;
            cp_async16(sa + SWZ(row * 128 + c8 * 16),
                       A + (size_t)(m0 + row) * K + kb + c8 * 8);
        }
        #pragma unroll
        for (int i = 0; i < 4; i++) {
            int idx = i * 256 + tid;
            int row = idx >> 3, c8 = idx & 7;
            cp_async16(sa + A_ST + SWZ(row * 128 + c8 * 16),
                       W + (size_t)(n0 + row) * K + kb + c8 * 8);
        }
        cp_commit();
    };

    #pragma unroll
    for (int s = 0; s < NSTG - 1; s++) load_stage(s, s);

    for (int k0 = 0; k0 < nk; k0++) {
        cp_wait<NSTG - 2>();
        __syncthreads();
        if (k0 + NSTG - 1 < nk) load_stage((k0 + NSTG - 1) % NSTG, k0 + NSTG - 1);

        uint32_t saA = sbase + (k0 % NSTG) * ST;
        uint32_t saB = saA + A_ST;

        #pragma unroll
        for (int kk = 0; kk < 4; kk++) {
            int kc = kk * 16;
            uint32_t af[MT][4], bf[8][2];
            #pragma unroll
            for (int mt = 0; mt < MT; mt++) {
                int row = wm * (16 * MT) + mt * 16 + (lane & 15);
                int colh = kc + ((lane >> 4) << 3);
                ldsm_x4(af[mt], saA + SWZ(row * 128 + colh * 2));
            }
            #pragma unroll
            for (int np = 0; np < 4; np++) {
                uint32_t r[4];
                int n = wn * 64 + np * 16 + (lane & 7) + ((lane >> 4) << 3);
                int colh = kc + (((lane >> 3) & 1) << 3);
                ldsm_x4(r, saB + SWZ(n * 128 + colh * 2));
                bf[np * 2 + 0][0] = r[0]; bf[np * 2 + 0][1] = r[1];
                bf[np * 2 + 1][0] = r[2]; bf[np * 2 + 1][1] = r[3];
            }
            #pragma unroll
            for (int mt = 0; mt < MT; mt++)
                #pragma unroll
                for (int nt = 0; nt < 8; nt++)
                    mma_f16(acc[mt][nt], af[mt], bf[nt]);
        }
        // no trailing __syncthreads: top-of-loop cp_wait+sync suffices
    }

    int g = lane >> 2, t = lane & 3;
    #pragma unroll
    for (int mt = 0; mt < MT; mt++) {
        #pragma unroll
        for (int nt = 0; nt < 8; nt++) {
            int col = n0 + wn * 64 + nt * 8 + 2 * t;
            int row = m0 + wm * (16 * MT) + mt * 16 + g;
            if (MODE == 0) {
                float2 b2 = *reinterpret_cast<const float2*>(&bias0[col]);
                #pragma unroll
                for (int hr = 0; hr < 2; hr++) {
                    size_t off = (size_t)(row + hr * 8) * N + col;
                    float2 v;
                    v.x = acc[mt][nt][hr * 2 + 0] + b2.x;
                    v.y = acc[mt][nt][hr * 2 + 1] + b2.y;
                    if (resid) {
                        float2 q = *reinterpret_cast<const float2*>(&resid[off]);
                        v.x += q.x; v.y += q.y;
                    }
                    *reinterpret_cast<float2*>(&((float*)outp)[off]) = v;
                }
            } else {
                int h = col >> 1;
                float bf0 = bias0[h], bf1 = bias1[h];
                #pragma unroll
                for (int hr = 0; hr < 2; hr++) {
                    size_t off = (size_t)(row + hr * 8) * HQ + h;
                    float c0 = acc[mt][nt][hr * 2 + 0] + bf0;
                    float c1 = acc[mt][nt][hr * 2 + 1] + bf1;
                    if (MODE == 1) {
                        float decay = (float)h * (1.0f / (float)(HQ - 1));
                        float rem = decay / (1.0f + expf(-c0));
                        float z = tanhf(c1) * rem;
                        ((__half2*)outp)[off] = __floats2half2_rn(rem, z);
                    } else {
                        float ff = c0 * c1 / (1.0f + expf(-c1));
                        ((__half*)outp)[off] = __float2half_rn(ff);
                    }
                }
            }
        }
    }
}

// ---------------- conversions / elementwise ----------------
// One launch converts all weights. grid = (2048, 4):
//  y=0: interleave(w_f, w_i) -> seg 0..1; y=1: interleave(w_fc, w_fa) -> seg 2..3
//  y=2: w_ho -> seg 4;  y=3: w_fo -> seg 5
__global__ void wconv_all(const float* __restrict__ w_f,  const float* __restrict__ w_i,
                          const float* __restrict__ w_fc, const float* __restrict__ w_fa,
                          const float* __restrict__ w_ho, const float* __restrict__ w_fo,
                          __half* __restrict__ wh)
{
    const size_t WSL = (size_t)HQ * DQ;
    size_t i4 = ((size_t)blockIdx.x * blockDim.x + threadIdx.x) * 4;
    int seg = blockIdx.y;
    if (seg < 2) {
        const float* a = seg ? w_fc : w_f;
        const float* b = seg ? w_fa : w_i;
        __half* out = wh + (size_t)seg * 2 * WSL;
        int j = (int)(i4 >> 10);
        int k = (int)(i4 & (DQ - 1));
        float4 va = *reinterpret_cast<const float4*>(a + i4);
        float4 vb = *reinterpret_cast<const float4*>(b + i4);
        __half2* oa = reinterpret_cast<__half2*>(out + ((size_t)(2 * j) * DQ + k));
        __half2* ob = reinterpret_cast<__half2*>(out + ((size_t)(2 * j + 1) * DQ + k));
        oa[0] = __floats2half2_rn(va.x, va.y);
        oa[1] = __floats2half2_rn(va.z, va.w);
        ob[0] = __floats2half2_rn(vb.x, vb.y);
        ob[1] = __floats2half2_rn(vb.z, vb.w);
    } else {
        const float* w = (seg == 2) ? w_ho : w_fo;
        __half* out = wh + (size_t)(seg + 2) * WSL;
        float4 v = *reinterpret_cast<const float4*>(w + i4);
        __half2* o = reinterpret_cast<__half2*>(out + i4);
        o[0] = __floats2half2_rn(v.x, v.y);
        o[1] = __floats2half2_rn(v.z, v.w);
    }
}

__global__ void rmsnorm_h(const float* __restrict__ x,
                          const float* __restrict__ g,
                          __half* __restrict__ out)
{
    int row = blockIdx.x, tid = threadIdx.x;
    float4 v = reinterpret_cast<const float4*>(x + (size_t)row * DQ)[tid];
    float s = v.x * v.x + v.y * v.y + v.z * v.z + v.w * v.w;
    #pragma unroll
    for (int o = 16; o > 0; o >>= 1) s += __shfl_xor_sync(0xFFFFFFFFu, s, o);
    __shared__ float red[8];
    __shared__ float scale_s;
    if ((tid & 31) == 0) red[tid >> 5] = s;
    __syncthreads();
    if (tid == 0) {
        float tt = 0.f;
        #pragma unroll
        for (int i = 0; i < 8; i++) tt += red[i];
        scale_s = rsqrtf(tt * (1.0f / DQ) + 1e-6f);
    }
    __syncthreads();
    float sc = scale_s;
    float4 gg = reinterpret_cast<const float4*>(g)[tid];
    __half2* o2 = reinterpret_cast<__half2*>(out + (size_t)row * DQ) + tid * 2;
    o2[0] = __floats2half2_rn(v.x * sc * gg.x, v.y * sc * gg.y);
    o2[1] = __floats2half2_rn(v.z * sc * gg.z, v.w * sc * gg.w);
}

// chunked scan over precomputed __half2(rem, z): 16 chunks x 256 steps
__global__ void scan_p1(const __half2* __restrict__ rz,
                        float* __restrict__ sA, float* __restrict__ sB)
{
    int tg = blockIdx.x * blockDim.x + threadIdx.x;
    int chunk = tg >> 13, c = tg & 8191;
    int b = c >> 11, hh = c & (HQ - 1);
    size_t base = ((size_t)b * LQ + chunk * 256) * HQ + hh;
    float Aa = 1.f, Bb = 0.f;
    #pragma unroll 4
    for (int t = 0; t < 256; t++) {
        float2 v = __half22float2(rz[base + (size_t)t * HQ]);
        float f = 1.0f - v.x;
        Bb = fmaf(f, Bb, v.y);
        Aa *= f;
    }
    sA[tg] = Aa; sB[tg] = Bb;
}

__global__ void scan_p2(const float* __restrict__ h0,
                        const float* __restrict__ sA, const float* __restrict__ sB,
                        float* __restrict__ sS, float* __restrict__ hlast)
{
    int c = blockIdx.x * blockDim.x + threadIdx.x;
    float h = h0[c];
    #pragma unroll
    for (int k = 0; k < 16; k++) {
        sS[k * 8192 + c] = h;
        h = fmaf(sA[k * 8192 + c], h, sB[k * 8192 + c]);
    }
    hlast[c] = h;
}

__global__ void scan_p3(const __half2* __restrict__ rz,
                        const float* __restrict__ sS, __half* __restrict__ out)
{
    int tg = blockIdx.x * blockDim.x + threadIdx.x;
    int chunk = tg >> 13, c = tg & 8191;
    int b = c >> 11, hh = c & (HQ - 1);
    size_t base = ((size_t)b * LQ + chunk * 256) * HQ + hh;
    float h = sS[tg];
    #pragma unroll 4
    for (int t = 0; t < 256; t++) {
        size_t i = base + (size_t)t * HQ;
        float2 v = __half22float2(rz[i]);
        h = fmaf(1.0f - v.x, h, v.y);
        out[i] = __float2half_rn(h);
    }
}

// ---------------- launch ----------------
extern "C" void kernel_launch(void* const* d_in, const int* in_sizes, int n_in,
                              void* d_out, int out_size)
{
    const float* x      = (const float*)d_in[0];
    const float* hidden = (const float*)d_in[1];
    const float* w_f    = (const float*)d_in[2];
    const float* b_f    = (const float*)d_in[3];
    const float* w_i    = (const float*)d_in[4];
    const float* b_i    = (const float*)d_in[5];
    const float* w_ho   = (const float*)d_in[6];
    const float* b_ho   = (const float*)d_in[7];
    const float* w_fc   = (const float*)d_in[8];
    const float* b_fc   = (const float*)d_in[9];
    const float* w_fa   = (const float*)d_in[10];
    const float* b_fa   = (const float*)d_in[11];
    const float* w_fo   = (const float*)d_in[12];
    const float* b_fo   = (const float*)d_in[13];
    const float* g1     = (const float*)d_in[14];
    const float* g2     = (const float*)d_in[15];

    float* out_main  = (float*)d_out;
    float* out_hlast = out_main + (size_t)BLQ * DQ;

    __half *xnh, *hh, *wh;
    __half2* rz;
    float *x1, *sA, *sB, *sS;
    cudaGetSymbolAddress((void**)&xnh, g_xnh);
    cudaGetSymbolAddress((void**)&hh,  g_hh);
    cudaGetSymbolAddress((void**)&wh,  g_wh);
    cudaGetSymbolAddress((void**)&rz,  g_rz);
    cudaGetSymbolAddress((void**)&x1,  g_x1);
    cudaGetSymbolAddress((void**)&sA,  g_sA);
    cudaGetSymbolAddress((void**)&sB,  g_sB);
    cudaGetSymbolAddress((void**)&sS,  g_sS);

    const size_t WSL = (size_t)HQ * DQ;   // 2M halves
    __half* wpfi   = wh + 0 * WSL;        // interleaved [4096,1024]
    __half* wpfcfa = wh + 2 * WSL;        // interleaved [4096,1024]
    __half* whho   = wh + 4 * WSL;        // [1024,2048]
    __half* whfo   = wh + 5 * WSL;        // [1024,2048]

    // All GEMMs now MT=2, NST=3 -> 3*(16384+16384)=98304 B, 2 CTAs/SM
    const int SMEM_G = 3 * (16384 + 16384);
    cudaFuncSetAttribute(gemm_h<0,2,3>, cudaFuncAttributeMaxDynamicSharedMemorySize, SMEM_G);
    cudaFuncSetAttribute(gemm_h<1,2,3>, cudaFuncAttributeMaxDynamicSharedMemorySize, SMEM_G);
    cudaFuncSetAttribute(gemm_h<2,2,3>, cudaFuncAttributeMaxDynamicSharedMemorySize, SMEM_G);

    wconv_all<<<dim3(2048, 4), 256>>>(w_f, w_i, w_fc, w_fa, w_ho, w_fo, wh);

    dim3 gPair(2 * HQ / 128, BLQ / 128);   // (32, 128)
    dim3 gHD(DQ / 128, BLQ / 128);         // (8, 128)

    rmsnorm_h<<<BLQ, 256>>>(x, g1, xnh);
    gemm_h<1,2,3><<<gPair, 256, SMEM_G>>>(xnh, DQ, wpfi, b_f, b_i, nullptr, rz, HQ);
    scan_p1<<<512, 256>>>(rz, sA, sB);
    scan_p2<<<32, 256>>>(hidden, sA, sB, sS, out_hlast);
    scan_p3<<<512, 256>>>(rz, sS, hh);
    gemm_h<0,2,3><<<gHD, 256, SMEM_G>>>(hh, HQ, whho, b_ho, nullptr, x, x1, DQ);
    rmsnorm_h<<<BLQ, 256>>>(x1, g2, xnh);
    gemm_h<2,2,3><<<gPair, 256, SMEM_G>>>(xnh, DQ, wpfcfa, b_fc, b_fa, nullptr, hh, HQ);
    gemm_h<0,2,3><<<gHD, 256, SMEM_G>>>(hh, HQ, whfo, b_fo, nullptr, x1, out_main, DQ);
}